// round 14
// baseline (speedup 1.0000x reference)
#include <cuda_runtime.h>
#include <cuda_bf16.h>
#include <math.h>
#include <stdint.h>

#define N_NODES 20000
#define T_STEPS 8
#define E_EDGES 320000
#define ETOT    (E_EDGES + N_NODES)
#define NFEAT   512
#define HC      512
#define H_HEADS 4
#define C_CH    128
#define SLOPEV  0.2f

#define MT_TILES 157
#define NT_TILES 4
#define BK 32

// ---------------- scratch (batched across T) ----------------
__device__ uint32_t g_h16T[(size_t)T_STEPS * N_NODES * 256];    // bf16x2 h, 164 MB
__device__ float g_asrcT[T_STEPS * N_NODES * H_HEADS];
__device__ float g_adstT[T_STEPS * N_NODES * H_HEADS];
__device__ uint16_t g_B16h[512 * 512];   // [n][k]
__device__ uint16_t g_B16l[512 * 512];
__device__ uint16_t g_A16h[(size_t)T_STEPS * N_NODES * 512];    // 164 MB
// batched CSR
__device__ int g_degT[T_STEPS * N_NODES];
__device__ int g_rowptrT[T_STEPS * (N_NODES + 1)];
__device__ int g_fillT[T_STEPS * N_NODES];
__device__ int g_colT[(size_t)T_STEPS * ETOT];

__device__ __forceinline__ float leaky(float x) { return x >= 0.f ? x : SLOPEV * x; }

__device__ __forceinline__ uint32_t smem_u32(const void* p) {
    uint32_t a;
    asm("{ .reg .u64 t; cvta.to.shared.u64 t, %1; cvt.u32.u64 %0, t; }" : "=r"(a) : "l"(p));
    return a;
}
__device__ __forceinline__ void ldsm_x4(uint32_t& r0, uint32_t& r1, uint32_t& r2, uint32_t& r3,
                                        uint32_t addr) {
    asm volatile("ldmatrix.sync.aligned.m8n8.x4.shared.b16 {%0,%1,%2,%3}, [%4];"
                 : "=r"(r0), "=r"(r1), "=r"(r2), "=r"(r3) : "r"(addr));
}
__device__ __forceinline__ void mma16816(float* c, const uint32_t* a, const uint32_t* b) {
    asm volatile(
        "mma.sync.aligned.m16n8k16.row.col.f32.bf16.bf16.f32 "
        "{%0,%1,%2,%3}, {%4,%5,%6,%7}, {%8,%9}, {%0,%1,%2,%3};"
        : "+f"(c[0]), "+f"(c[1]), "+f"(c[2]), "+f"(c[3])
        : "r"(a[0]), "r"(a[1]), "r"(a[2]), "r"(a[3]), "r"(b[0]), "r"(b[1]));
}
__device__ __forceinline__ uint32_t pack_hi2(float v0, float v1) {
    __nv_bfloat162 p = __floats2bfloat162_rn(v0, v1);
    return *reinterpret_cast<uint32_t*>(&p);
}
__device__ __forceinline__ void cp16(uint32_t dst, const void* src) {
    asm volatile("cp.async.cg.shared.global [%0], [%1], 16;" :: "r"(dst), "l"(src));
}
#define CP_COMMIT() asm volatile("cp.async.commit_group;" ::: "memory")
#define CP_WAIT0()  asm volatile("cp.async.wait_group 0;" ::: "memory")
#define CP_WAIT1()  asm volatile("cp.async.wait_group 1;" ::: "memory")

// ---------------- 0a) convert W -> bf16 hi/lo, [n][k] ----------------
__global__ void conv_B(const float* __restrict__ W) {
    int i = blockIdx.x * blockDim.x + threadIdx.x;
    if (i >= 512 * 512) return;
    int k = i >> 9, n = i & 511;
    float v = W[(size_t)k * 512 + n];
    __nv_bfloat16 h = __float2bfloat16(v);
    __nv_bfloat16 l = __float2bfloat16(v - __bfloat162float(h));
    g_B16h[(size_t)n * 512 + k] = *reinterpret_cast<uint16_t*>(&h);
    g_B16l[(size_t)n * 512 + k] = *reinterpret_cast<uint16_t*>(&l);
}

// ---------------- 0b) convert ALL fts -> bf16 (hi only) ----------------
__global__ __launch_bounds__(256) void conv_A(const float* __restrict__ A) {
    size_t i = (size_t)blockIdx.x * blockDim.x + threadIdx.x;
    if (i >= (size_t)T_STEPS * N_NODES * 128) return;
    float4 v = ((const float4*)A)[i];
    uint2 hi = make_uint2(pack_hi2(v.x, v.y), pack_hi2(v.z, v.w));
    ((uint2*)g_A16h)[i] = hi;
}

// ---------------- 1) GEMM: 3-stage cp.async pipeline, fused att epilogue ----------------
#define BF_PITCH  40
#define STG       (128 * BF_PITCH * 2)   // 10240 B
#define OFF_A     0
#define OFF_BH    (3 * STG)
#define OFF_BL    (6 * STG)
#define GEMM_SMEM_TOT (9 * STG)          // 92160

__device__ __forceinline__ void load_stage(uint32_t sb, int tid, size_t aBase, int mt, int nt,
                                           int buf, int k0) {
#pragma unroll
    for (int c = 0; c < 2; c++) {
        int idx = tid + c * 256;
        int row = idx >> 2, ch = idx & 3;
        int node = mt * 128 + row;
        if (node > N_NODES - 1) node = N_NODES - 1;
        uint32_t doff = buf * STG + row * (BF_PITCH * 2) + ch * 16;
        const uint16_t* sa = g_A16h + aBase + (size_t)node * 512 + k0 + ch * 8;
        cp16(sb + OFF_A + doff, sa);
        const uint16_t* sbh = g_B16h + (size_t)(nt * 128 + row) * 512 + k0 + ch * 8;
        const uint16_t* sbl = g_B16l + (size_t)(nt * 128 + row) * 512 + k0 + ch * 8;
        cp16(sb + OFF_BH + doff, sbh);
        cp16(sb + OFF_BL + doff, sbl);
    }
}

__global__ __launch_bounds__(256, 2) void gemm_mma(const float* __restrict__ att_src,
                                                   const float* __restrict__ att_dst) {
    extern __shared__ __align__(16) unsigned char sm[];
    uint32_t sb = smem_u32(sm);
    const int tid = threadIdx.x, warp = tid >> 5, lane = tid & 31;
    const int mt = blockIdx.y, nt = blockIdx.x, t = blockIdx.z;
    const int warpM = warp & 1, warpN = warp >> 1;
    const size_t aBase = (size_t)t * N_NODES * 512;

    float acc[4][4][4];
#pragma unroll
    for (int i = 0; i < 4; i++)
#pragma unroll
        for (int j = 0; j < 4; j++)
#pragma unroll
            for (int q = 0; q < 4; q++) acc[i][j][q] = 0.f;

    const uint32_t aB = sb + OFF_A;
    const uint32_t bhB = sb + OFF_BH, blB = sb + OFF_BL;
    const int aLdRow = warpM * 64 + (lane & 7) + ((lane >> 3) & 1) * 8;
    const int aLdK   = (lane >> 4) * 8;
    const int bLdRow = warpN * 32 + (lane & 7) + ((lane >> 4) & 1) * 8;
    const int bLdK   = ((lane >> 3) & 1) * 8;

    load_stage(sb, tid, aBase, mt, nt, 0, 0);
    CP_COMMIT();
    load_stage(sb, tid, aBase, mt, nt, 1, BK);
    CP_COMMIT();

    int cur = 0;
    for (int it = 0; it < 16; it++) {
        if (it < 15) CP_WAIT1(); else CP_WAIT0();
        __syncthreads();
        if (it + 2 < 16) {
            int nb = (it + 2) % 3;
            load_stage(sb, tid, aBase, mt, nt, nb, (it + 2) * BK);
            CP_COMMIT();
        }

#pragma unroll
        for (int kk = 0; kk < 32; kk += 16) {
            uint32_t bh[2][4], bl[2][4];
#pragma unroll
            for (int nfp = 0; nfp < 2; nfp++) {
                uint32_t off = (uint32_t)(cur * STG + (bLdRow + nfp * 16) * (BF_PITCH * 2)
                                          + (kk + bLdK) * 2);
                ldsm_x4(bh[nfp][0], bh[nfp][1], bh[nfp][2], bh[nfp][3], bhB + off);
                ldsm_x4(bl[nfp][0], bl[nfp][1], bl[nfp][2], bl[nfp][3], blB + off);
            }
#pragma unroll
            for (int mf = 0; mf < 4; mf++) {
                uint32_t off = (uint32_t)(cur * STG + (aLdRow + mf * 16) * (BF_PITCH * 2)
                                          + (kk + aLdK) * 2);
                uint32_t ah[4];
                ldsm_x4(ah[0], ah[1], ah[2], ah[3], aB + off);
#pragma unroll
                for (int nf = 0; nf < 4; nf++) {
                    const uint32_t* bfrag_h = &bh[nf >> 1][(nf & 1) * 2];
                    const uint32_t* bfrag_l = &bl[nf >> 1][(nf & 1) * 2];
                    mma16816(acc[mf][nf], ah, bfrag_h);
                    mma16816(acc[mf][nf], ah, bfrag_l);
                }
            }
        }
        cur = (cur + 1) % 3;
    }

    // ---- write h in bf16x2 ----
    uint32_t* hOut = g_h16T + (size_t)t * N_NODES * 256;
    const int r0 = lane >> 2, c0 = (lane & 3) * 2;
#pragma unroll
    for (int mf = 0; mf < 4; mf++) {
#pragma unroll
        for (int nf = 0; nf < 4; nf++) {
            int row = mt * 128 + warpM * 64 + mf * 16 + r0;
            int col = nt * 128 + warpN * 32 + nf * 8 + c0;
            if (row < N_NODES)
                hOut[(size_t)row * 256 + (col >> 1)] = pack_hi2(acc[mf][nf][0], acc[mf][nf][1]);
            if (row + 8 < N_NODES)
                hOut[(size_t)(row + 8) * 256 + (col >> 1)] = pack_hi2(acc[mf][nf][2], acc[mf][nf][3]);
        }
    }

    // ---- fused attention coefficients ----
    float asv[4][2], adv[4][2];
#pragma unroll
    for (int nf = 0; nf < 4; nf++) {
#pragma unroll
        for (int e = 0; e < 2; e++) {
            int cidx = nt * 128 + warpN * 32 + nf * 8 + c0 + e;
            asv[nf][e] = __ldg(&att_src[cidx]);
            adv[nf][e] = __ldg(&att_dst[cidx]);
        }
    }
    __syncthreads();   // smem reuse: all stages consumed
    float* attS = (float*)sm;            // [128][4]
    float* attD = (float*)sm + 512;      // [128][4]
#pragma unroll
    for (int mf = 0; mf < 4; mf++) {
#pragma unroll
        for (int half = 0; half < 2; half++) {
            float s = 0.f, d = 0.f;
#pragma unroll
            for (int nf = 0; nf < 4; nf++) {
                s = fmaf(acc[mf][nf][half * 2 + 0], asv[nf][0], s);
                s = fmaf(acc[mf][nf][half * 2 + 1], asv[nf][1], s);
                d = fmaf(acc[mf][nf][half * 2 + 0], adv[nf][0], d);
                d = fmaf(acc[mf][nf][half * 2 + 1], adv[nf][1], d);
            }
            s += __shfl_xor_sync(0xffffffffu, s, 1);
            s += __shfl_xor_sync(0xffffffffu, s, 2);
            d += __shfl_xor_sync(0xffffffffu, d, 1);
            d += __shfl_xor_sync(0xffffffffu, d, 2);
            if ((lane & 3) == 0) {
                int rowL = warpM * 64 + mf * 16 + half * 8 + r0;
                attS[rowL * 4 + warpN] = s;
                attD[rowL * 4 + warpN] = d;
            }
        }
    }
    __syncthreads();
    {
        int rowL = tid >> 1, which = tid & 1;
        int node = mt * 128 + rowL;
        if (node < N_NODES) {
            const float* base = which ? attD : attS;
            float v = base[rowL * 4 + 0] + base[rowL * 4 + 1] + base[rowL * 4 + 2] + base[rowL * 4 + 3];
            float* dst = which ? g_adstT : g_asrcT;
            dst[((size_t)t * N_NODES + node) * H_HEADS + nt] = v;
        }
    }
}

// ---------------- 3) batched CSR build ----------------
__global__ void zero_degT() {
    int i = blockIdx.x * blockDim.x + threadIdx.x;
    if (i < T_STEPS * N_NODES) g_degT[i] = 0;
}

__global__ void degT_kernel(const int* __restrict__ graph) {
    int i = blockIdx.x * blockDim.x + threadIdx.x;
    if (i >= T_STEPS * ETOT) return;
    int t = i / ETOT, e = i - t * ETOT;
    int d = (e < E_EDGES) ? graph[(size_t)t * 2 * E_EDGES + E_EDGES + e] : (e - E_EDGES);
    atomicAdd(&g_degT[t * N_NODES + d], 1);
}

__global__ __launch_bounds__(1024) void scanT_kernel() {
    __shared__ int s[1024];
    int t = blockIdx.x;
    const int* deg = g_degT + t * N_NODES;
    int* rowptr = g_rowptrT + t * (N_NODES + 1);
    int* fill = g_fillT + t * N_NODES;
    int tid = threadIdx.x;
    const int PER = 20;
    int base = tid * PER;
    int vals[PER];
    int run = 0;
#pragma unroll
    for (int i = 0; i < PER; i++) {
        int idx = base + i;
        int v = (idx < N_NODES) ? deg[idx] : 0;
        vals[i] = run;
        run += v;
    }
    s[tid] = run;
    __syncthreads();
    for (int off = 1; off < 1024; off <<= 1) {
        int v = (tid >= off) ? s[tid - off] : 0;
        __syncthreads();
        s[tid] += v;
        __syncthreads();
    }
    int prev = (tid == 0) ? 0 : s[tid - 1];
#pragma unroll
    for (int i = 0; i < PER; i++) {
        int idx = base + i;
        if (idx < N_NODES) {
            int r = prev + vals[i];
            rowptr[idx] = r;
            fill[idx] = r;
        }
    }
    if (tid == 1023) rowptr[N_NODES] = s[1023];
}

__global__ void scatterT_kernel(const int* __restrict__ graph) {
    int i = blockIdx.x * blockDim.x + threadIdx.x;
    if (i >= T_STEPS * ETOT) return;
    int t = i / ETOT, e = i - t * ETOT;
    int sidx, d;
    if (e < E_EDGES) {
        sidx = graph[(size_t)t * 2 * E_EDGES + e];
        d    = graph[(size_t)t * 2 * E_EDGES + E_EDGES + e];
    } else {
        sidx = d = e - E_EDGES;
    }
    int pos = atomicAdd(&g_fillT[t * N_NODES + d], 1);
    g_colT[(size_t)t * ETOT + pos] = sidx;
}

// ---------------- 4) aggregation: 8 nodes/block + fused z@W1 + fused final ----------------
// Block (bx, t) covers nodes 8bx..8bx+7 of step t == reshape row r = t*2500 + bx.
__global__ __launch_bounds__(256) void aggregate_kernel(const float* __restrict__ b_gat,
                                                        const float* __restrict__ W1,
                                                        const float* __restrict__ b1,
                                                        const float* __restrict__ W2,
                                                        const float* __restrict__ b2,
                                                        float* __restrict__ out) {
    __shared__ __align__(16) float z_sm[8][C_CH];
    __shared__ float red[2][8];
    int warp = threadIdx.x >> 5;
    int lane = threadIdx.x & 31;
    int t = blockIdx.y;
    int n = blockIdx.x * 8 + warp;

    const int* rowptr = g_rowptrT + t * (N_NODES + 1);
    const int* col = g_colT + (size_t)t * ETOT;
    const float* asrc = g_asrcT + (size_t)t * N_NODES * H_HEADS;
    const uint32_t* h16 = g_h16T + (size_t)t * N_NODES * 256;

    int beg = rowptr[n];
    int end = rowptr[n + 1];
    const float4 ad = *(const float4*)&g_adstT[((size_t)t * N_NODES + n) * H_HEADS];

    float4 acc0 = make_float4(0.f, 0.f, 0.f, 0.f), acc1 = acc0, acc2 = acc0, acc3 = acc0;
    float s0 = 0.f, s1 = 0.f, s2 = 0.f, s3 = 0.f;
    const int lOff = lane * 2;

    int k = beg;
    for (; k + 2 <= end; k += 2) {
        int sa = col[k], sb2 = col[k + 1];
        const float4 ea = *(const float4*)&asrc[sa * H_HEADS];
        const float4 eb = *(const float4*)&asrc[sb2 * H_HEADS];
        float wa0 = __expf(leaky(ea.x + ad.x)), wa1 = __expf(leaky(ea.y + ad.y));
        float wa2 = __expf(leaky(ea.z + ad.z)), wa3 = __expf(leaky(ea.w + ad.w));
        float wb0 = __expf(leaky(eb.x + ad.x)), wb1 = __expf(leaky(eb.y + ad.y));
        float wb2 = __expf(leaky(eb.z + ad.z)), wb3 = __expf(leaky(eb.w + ad.w));
        const uint32_t* ha = h16 + (size_t)sa * 256 + lOff;
        const uint32_t* hb = h16 + (size_t)sb2 * 256 + lOff;
        uint2 ua0 = *(const uint2*)(ha);
        uint2 ua1 = *(const uint2*)(ha + 64);
        uint2 ua2 = *(const uint2*)(ha + 128);
        uint2 ua3 = *(const uint2*)(ha + 192);
        uint2 ub0 = *(const uint2*)(hb);
        uint2 ub1 = *(const uint2*)(hb + 64);
        uint2 ub2 = *(const uint2*)(hb + 128);
        uint2 ub3 = *(const uint2*)(hb + 192);
        s0 += wa0 + wb0; s1 += wa1 + wb1; s2 += wa2 + wb2; s3 += wa3 + wb3;
#define ACCH(ACC, W_A, W_B, UA, UB)                                              \
        {                                                                        \
            float2 la = __bfloat1622float2(*(__nv_bfloat162*)&UA.x);             \
            float2 ha2 = __bfloat1622float2(*(__nv_bfloat162*)&UA.y);            \
            float2 lb = __bfloat1622float2(*(__nv_bfloat162*)&UB.x);             \
            float2 hb2 = __bfloat1622float2(*(__nv_bfloat162*)&UB.y);            \
            ACC.x = fmaf(W_A, la.x, fmaf(W_B, lb.x, ACC.x));                     \
            ACC.y = fmaf(W_A, la.y, fmaf(W_B, lb.y, ACC.y));                     \
            ACC.z = fmaf(W_A, ha2.x, fmaf(W_B, hb2.x, ACC.z));                   \
            ACC.w = fmaf(W_A, ha2.y, fmaf(W_B, hb2.y, ACC.w));                   \
        }
        ACCH(acc0, wa0, wb0, ua0, ub0)
        ACCH(acc1, wa1, wb1, ua1, ub1)
        ACCH(acc2, wa2, wb2, ua2, ub2)
        ACCH(acc3, wa3, wb3, ua3, ub3)
    }
    if (k < end) {
        int sa = col[k];
        const float4 ea = *(const float4*)&asrc[sa * H_HEADS];
        float wa0 = __expf(leaky(ea.x + ad.x)), wa1 = __expf(leaky(ea.y + ad.y));
        float wa2 = __expf(leaky(ea.z + ad.z)), wa3 = __expf(leaky(ea.w + ad.w));
        const uint32_t* ha = h16 + (size_t)sa * 256 + lOff;
        uint2 ua0 = *(const uint2*)(ha);
        uint2 ua1 = *(const uint2*)(ha + 64);
        uint2 ua2 = *(const uint2*)(ha + 128);
        uint2 ua3 = *(const uint2*)(ha + 192);
        s0 += wa0; s1 += wa1; s2 += wa2; s3 += wa3;
#define ACC1(ACC, W_A, UA)                                                       \
        {                                                                        \
            float2 la = __bfloat1622float2(*(__nv_bfloat162*)&UA.x);             \
            float2 ha2 = __bfloat1622float2(*(__nv_bfloat162*)&UA.y);            \
            ACC.x = fmaf(W_A, la.x, ACC.x);                                      \
            ACC.y = fmaf(W_A, la.y, ACC.y);                                      \
            ACC.z = fmaf(W_A, ha2.x, ACC.z);                                     \
            ACC.w = fmaf(W_A, ha2.y, ACC.w);                                     \
        }
        ACC1(acc0, wa0, ua0)
        ACC1(acc1, wa1, ua1)
        ACC1(acc2, wa2, ua2)
        ACC1(acc3, wa3, ua3)
    }
    float i0 = 1.f / (s0 + 1e-16f), i1 = 1.f / (s1 + 1e-16f);
    float i2 = 1.f / (s2 + 1e-16f), i3 = 1.f / (s3 + 1e-16f);

    // head mean + bias + leaky -> z_sm[warp]
    {
        const float4 bg = *(const float4*)&b_gat[lane * 4];
        float4 z;
        z.x = leaky(0.25f * (acc0.x * i0 + acc1.x * i1 + acc2.x * i2 + acc3.x * i3) + bg.x);
        z.y = leaky(0.25f * (acc0.y * i0 + acc1.y * i1 + acc2.y * i2 + acc3.y * i3) + bg.y);
        z.z = leaky(0.25f * (acc0.z * i0 + acc1.z * i1 + acc2.z * i2 + acc3.z * i3) + bg.z);
        z.w = leaky(0.25f * (acc0.w * i0 + acc1.w * i1 + acc2.w * i2 + acc3.w * i3) + bg.w);
        *(float4*)&z_sm[warp][lane * 4] = z;
    }
    __syncthreads();

    // fused: lp = leaky(z @ W1 + b1) for 8 nodes, then dot with W2 + block reduce
    float p0 = 0.f, p1 = 0.f;
    {
        int j    = threadIdx.x & 127;
        int half = threadIdx.x >> 7;
        float a0 = b1[j], a1 = a0, a2 = a0, a3 = a0;
        const float* z0 = z_sm[half * 4 + 0];
        const float* z1 = z_sm[half * 4 + 1];
        const float* z2 = z_sm[half * 4 + 2];
        const float* z3 = z_sm[half * 4 + 3];
#pragma unroll 8
        for (int kk = 0; kk < 128; kk++) {
            float wv = __ldg(&W1[kk * 128 + j]);
            a0 = fmaf(z0[kk], wv, a0);
            a1 = fmaf(z1[kk], wv, a1);
            a2 = fmaf(z2[kk], wv, a2);
            a3 = fmaf(z3[kk], wv, a3);
        }
        float lp[4] = {leaky(a0), leaky(a1), leaky(a2), leaky(a3)};
        int base_i = (half * 4) * 128 + j;
#pragma unroll
        for (int nl = 0; nl < 4; nl++) {
            int i = base_i + nl * 128;
            p0 = fmaf(lp[nl], __ldg(&W2[i * 2 + 0]), p0);
            p1 = fmaf(lp[nl], __ldg(&W2[i * 2 + 1]), p1);
        }
    }
#pragma unroll
    for (int o = 16; o; o >>= 1) {
        p0 += __shfl_xor_sync(0xffffffffu, p0, o);
        p1 += __shfl_xor_sync(0xffffffffu, p1, o);
    }
    if (lane == 0) { red[0][warp] = p0; red[1][warp] = p1; }
    __syncthreads();
    if (threadIdx.x == 0) {
        float f0 = b2[0], f1 = b2[1];
#pragma unroll
        for (int w = 0; w < 8; w++) { f0 += red[0][w]; f1 += red[1][w]; }
        float m = fmaxf(f0, f1);
        float lse = m + logf(expf(f0 - m) + expf(f1 - m));
        int r = t * (N_NODES / 8) + blockIdx.x;
        out[r * 2 + 0] = f0 - lse;
        out[r * 2 + 1] = f1 - lse;
    }
}

// ---------------- launch ----------------
extern "C" void kernel_launch(void* const* d_in, const int* in_sizes, int n_in,
                              void* d_out, int out_size) {
    int base = 2;
    if (n_in >= 11 && in_sizes[2] <= 1) base = 3;

    const float* fts     = (const float*)d_in[0];
    const int*   graph   = (const int*)d_in[1];
    const float* W_gat   = (const float*)d_in[base + 0];
    const float* att_src = (const float*)d_in[base + 1];
    const float* att_dst = (const float*)d_in[base + 2];
    const float* b_gat   = (const float*)d_in[base + 3];
    const float* W1      = (const float*)d_in[base + 4];
    const float* b1      = (const float*)d_in[base + 5];
    const float* W2      = (const float*)d_in[base + 6];
    const float* b2      = (const float*)d_in[base + 7];
    float* out = (float*)d_out;

    cudaFuncSetAttribute(gemm_mma, cudaFuncAttributeMaxDynamicSharedMemorySize, GEMM_SMEM_TOT);

    const int convGrid = (int)(((size_t)T_STEPS * N_NODES * 128 + 255) / 256);

    // gemm_mma kept as the 4th launch for the ncu window
    conv_B<<<(512 * 512 + 255) / 256, 256>>>(W_gat);
    conv_A<<<convGrid, 256>>>(fts);
    zero_degT<<<(T_STEPS * N_NODES + 255) / 256, 256>>>();
    gemm_mma<<<dim3(NT_TILES, MT_TILES, T_STEPS), 256, GEMM_SMEM_TOT>>>(att_src, att_dst);
    degT_kernel<<<(T_STEPS * ETOT + 255) / 256, 256>>>(graph);
    scanT_kernel<<<T_STEPS, 1024>>>();
    scatterT_kernel<<<(T_STEPS * ETOT + 255) / 256, 256>>>(graph);
    aggregate_kernel<<<dim3(N_NODES / 8, T_STEPS), 256>>>(b_gat, W1, b1, W2, b2, out);
}

// round 15
// speedup vs baseline: 1.0405x; 1.0405x over previous
#include <cuda_runtime.h>
#include <cuda_bf16.h>
#include <math.h>
#include <stdint.h>

#define N_NODES 20000
#define T_STEPS 8
#define E_EDGES 320000
#define ETOT    (E_EDGES + N_NODES)
#define NFEAT   512
#define HC      512
#define H_HEADS 4
#define C_CH    128
#define SLOPEV  0.2f

#define MT_TILES 157
#define NT_TILES 4
#define BK 64

// ---------------- scratch (batched across T) ----------------
__device__ uint32_t g_h16T[(size_t)T_STEPS * N_NODES * 256];    // bf16x2 h, 164 MB
__device__ float g_asrcT[T_STEPS * N_NODES * H_HEADS];
__device__ float g_adstT[T_STEPS * N_NODES * H_HEADS];
__device__ uint16_t g_B16h[512 * 512];   // [n][k]
__device__ uint16_t g_B16l[512 * 512];
__device__ uint16_t g_A16h[(size_t)T_STEPS * N_NODES * 512];    // 164 MB
// batched CSR
__device__ int g_degT[T_STEPS * N_NODES];
__device__ int g_rowptrT[T_STEPS * (N_NODES + 1)];
__device__ int g_fillT[T_STEPS * N_NODES];
__device__ int g_colT[(size_t)T_STEPS * ETOT];

__device__ __forceinline__ float leaky(float x) { return x >= 0.f ? x : SLOPEV * x; }

__device__ __forceinline__ uint32_t smem_u32(const void* p) {
    uint32_t a;
    asm("{ .reg .u64 t; cvta.to.shared.u64 t, %1; cvt.u32.u64 %0, t; }" : "=r"(a) : "l"(p));
    return a;
}
__device__ __forceinline__ void ldsm_x4(uint32_t& r0, uint32_t& r1, uint32_t& r2, uint32_t& r3,
                                        uint32_t addr) {
    asm volatile("ldmatrix.sync.aligned.m8n8.x4.shared.b16 {%0,%1,%2,%3}, [%4];"
                 : "=r"(r0), "=r"(r1), "=r"(r2), "=r"(r3) : "r"(addr));
}
__device__ __forceinline__ void mma16816(float* c, const uint32_t* a, const uint32_t* b) {
    asm volatile(
        "mma.sync.aligned.m16n8k16.row.col.f32.bf16.bf16.f32 "
        "{%0,%1,%2,%3}, {%4,%5,%6,%7}, {%8,%9}, {%0,%1,%2,%3};"
        : "+f"(c[0]), "+f"(c[1]), "+f"(c[2]), "+f"(c[3])
        : "r"(a[0]), "r"(a[1]), "r"(a[2]), "r"(a[3]), "r"(b[0]), "r"(b[1]));
}
__device__ __forceinline__ uint32_t pack_hi2(float v0, float v1) {
    __nv_bfloat162 p = __floats2bfloat162_rn(v0, v1);
    return *reinterpret_cast<uint32_t*>(&p);
}
__device__ __forceinline__ void cp16(uint32_t dst, const void* src) {
    asm volatile("cp.async.cg.shared.global [%0], [%1], 16;" :: "r"(dst), "l"(src));
}
#define CP_COMMIT() asm volatile("cp.async.commit_group;" ::: "memory")
#define CP_WAIT0()  asm volatile("cp.async.wait_group 0;" ::: "memory")

// ---------------- 0a) convert W -> bf16 hi/lo, [n][k] ----------------
__global__ void conv_B(const float* __restrict__ W) {
    int i = blockIdx.x * blockDim.x + threadIdx.x;
    if (i >= 512 * 512) return;
    int k = i >> 9, n = i & 511;
    float v = W[(size_t)k * 512 + n];
    __nv_bfloat16 h = __float2bfloat16(v);
    __nv_bfloat16 l = __float2bfloat16(v - __bfloat162float(h));
    g_B16h[(size_t)n * 512 + k] = *reinterpret_cast<uint16_t*>(&h);
    g_B16l[(size_t)n * 512 + k] = *reinterpret_cast<uint16_t*>(&l);
}

// ---------------- 0b) convert ALL fts -> bf16 (hi only) ----------------
__global__ __launch_bounds__(256) void conv_A(const float* __restrict__ A) {
    size_t i = (size_t)blockIdx.x * blockDim.x + threadIdx.x;
    if (i >= (size_t)T_STEPS * N_NODES * 128) return;
    float4 v = ((const float4*)A)[i];
    uint2 hi = make_uint2(pack_hi2(v.x, v.y), pack_hi2(v.z, v.w));
    ((uint2*)g_A16h)[i] = hi;
}

// ---------------- 1) GEMM: 2-stage cp.async, BK=64, fused att epilogue ----------------
#define BF_PITCH  72                     // bf16 elems per smem row (144 B)
#define STG       (128 * BF_PITCH * 2)   // 18432 B per array per stage
#define OFF_A     0
#define OFF_BH    (2 * STG)
#define OFF_BL    (4 * STG)
#define GEMM_SMEM_TOT (6 * STG)          // 110592

__device__ __forceinline__ void load_stage(uint32_t sb, int tid, size_t aBase, int mt, int nt,
                                           int buf, int k0) {
#pragma unroll
    for (int c = 0; c < 4; c++) {
        int idx = tid + c * 256;          // 0..1023
        int row = idx >> 3, ch = idx & 7; // 128 rows x 8 chunks of 16B
        int node = mt * 128 + row;
        if (node > N_NODES - 1) node = N_NODES - 1;
        uint32_t doff = buf * STG + row * (BF_PITCH * 2) + ch * 16;
        const uint16_t* sa = g_A16h + aBase + (size_t)node * 512 + k0 + ch * 8;
        cp16(sb + OFF_A + doff, sa);
        const uint16_t* sbh = g_B16h + (size_t)(nt * 128 + row) * 512 + k0 + ch * 8;
        const uint16_t* sbl = g_B16l + (size_t)(nt * 128 + row) * 512 + k0 + ch * 8;
        cp16(sb + OFF_BH + doff, sbh);
        cp16(sb + OFF_BL + doff, sbl);
    }
}

__global__ __launch_bounds__(256, 2) void gemm_mma(const float* __restrict__ att_src,
                                                   const float* __restrict__ att_dst) {
    extern __shared__ __align__(16) unsigned char sm[];
    uint32_t sb = smem_u32(sm);
    const int tid = threadIdx.x, warp = tid >> 5, lane = tid & 31;
    const int mt = blockIdx.y, nt = blockIdx.x, t = blockIdx.z;
    const int warpM = warp & 1, warpN = warp >> 1;
    const size_t aBase = (size_t)t * N_NODES * 512;

    float acc[4][4][4];
#pragma unroll
    for (int i = 0; i < 4; i++)
#pragma unroll
        for (int j = 0; j < 4; j++)
#pragma unroll
            for (int q = 0; q < 4; q++) acc[i][j][q] = 0.f;

    const uint32_t aB = sb + OFF_A;
    const uint32_t bhB = sb + OFF_BH, blB = sb + OFF_BL;
    const int aLdRow = warpM * 64 + (lane & 7) + ((lane >> 3) & 1) * 8;
    const int aLdK   = (lane >> 4) * 8;
    const int bLdRow = warpN * 32 + (lane & 7) + ((lane >> 4) & 1) * 8;
    const int bLdK   = ((lane >> 3) & 1) * 8;

    load_stage(sb, tid, aBase, mt, nt, 0, 0);
    CP_COMMIT();

    for (int it = 0; it < 8; it++) {
        const int cur = it & 1;
        CP_WAIT0();
        __syncthreads();
        if (it + 1 < 8) {
            load_stage(sb, tid, aBase, mt, nt, cur ^ 1, (it + 1) * BK);
            CP_COMMIT();
        }

#pragma unroll
        for (int kk = 0; kk < 64; kk += 16) {
            uint32_t bh[2][4], bl[2][4];
#pragma unroll
            for (int nfp = 0; nfp < 2; nfp++) {
                uint32_t off = (uint32_t)(cur * STG + (bLdRow + nfp * 16) * (BF_PITCH * 2)
                                          + (kk + bLdK) * 2);
                ldsm_x4(bh[nfp][0], bh[nfp][1], bh[nfp][2], bh[nfp][3], bhB + off);
                ldsm_x4(bl[nfp][0], bl[nfp][1], bl[nfp][2], bl[nfp][3], blB + off);
            }
#pragma unroll
            for (int mf = 0; mf < 4; mf++) {
                uint32_t off = (uint32_t)(cur * STG + (aLdRow + mf * 16) * (BF_PITCH * 2)
                                          + (kk + aLdK) * 2);
                uint32_t ah[4];
                ldsm_x4(ah[0], ah[1], ah[2], ah[3], aB + off);
#pragma unroll
                for (int nf = 0; nf < 4; nf++) {
                    const uint32_t* bfrag_h = &bh[nf >> 1][(nf & 1) * 2];
                    const uint32_t* bfrag_l = &bl[nf >> 1][(nf & 1) * 2];
                    mma16816(acc[mf][nf], ah, bfrag_h);
                    mma16816(acc[mf][nf], ah, bfrag_l);
                }
            }
        }
        __syncthreads();
    }

    // ---- write h in bf16x2 ----
    uint32_t* hOut = g_h16T + (size_t)t * N_NODES * 256;
    const int r0 = lane >> 2, c0 = (lane & 3) * 2;
#pragma unroll
    for (int mf = 0; mf < 4; mf++) {
#pragma unroll
        for (int nf = 0; nf < 4; nf++) {
            int row = mt * 128 + warpM * 64 + mf * 16 + r0;
            int col = nt * 128 + warpN * 32 + nf * 8 + c0;
            if (row < N_NODES)
                hOut[(size_t)row * 256 + (col >> 1)] = pack_hi2(acc[mf][nf][0], acc[mf][nf][1]);
            if (row + 8 < N_NODES)
                hOut[(size_t)(row + 8) * 256 + (col >> 1)] = pack_hi2(acc[mf][nf][2], acc[mf][nf][3]);
        }
    }

    // ---- fused attention coefficients ----
    float asv[4][2], adv[4][2];
#pragma unroll
    for (int nf = 0; nf < 4; nf++) {
#pragma unroll
        for (int e = 0; e < 2; e++) {
            int cidx = nt * 128 + warpN * 32 + nf * 8 + c0 + e;
            asv[nf][e] = __ldg(&att_src[cidx]);
            adv[nf][e] = __ldg(&att_dst[cidx]);
        }
    }
    float* attS = (float*)sm;            // [128][4]
    float* attD = (float*)sm + 512;      // [128][4]
#pragma unroll
    for (int mf = 0; mf < 4; mf++) {
#pragma unroll
        for (int half = 0; half < 2; half++) {
            float s = 0.f, d = 0.f;
#pragma unroll
            for (int nf = 0; nf < 4; nf++) {
                s = fmaf(acc[mf][nf][half * 2 + 0], asv[nf][0], s);
                s = fmaf(acc[mf][nf][half * 2 + 1], asv[nf][1], s);
                d = fmaf(acc[mf][nf][half * 2 + 0], adv[nf][0], d);
                d = fmaf(acc[mf][nf][half * 2 + 1], adv[nf][1], d);
            }
            s += __shfl_xor_sync(0xffffffffu, s, 1);
            s += __shfl_xor_sync(0xffffffffu, s, 2);
            d += __shfl_xor_sync(0xffffffffu, d, 1);
            d += __shfl_xor_sync(0xffffffffu, d, 2);
            if ((lane & 3) == 0) {
                int rowL = warpM * 64 + mf * 16 + half * 8 + r0;
                attS[rowL * 4 + warpN] = s;
                attD[rowL * 4 + warpN] = d;
            }
        }
    }
    __syncthreads();
    {
        int rowL = tid >> 1, which = tid & 1;
        int node = mt * 128 + rowL;
        if (node < N_NODES) {
            const float* base = which ? attD : attS;
            float v = base[rowL * 4 + 0] + base[rowL * 4 + 1] + base[rowL * 4 + 2] + base[rowL * 4 + 3];
            float* dst = which ? g_adstT : g_asrcT;
            dst[((size_t)t * N_NODES + node) * H_HEADS + nt] = v;
        }
    }
}

// ---------------- 3) batched CSR build ----------------
__global__ void zero_degT() {
    int i = blockIdx.x * blockDim.x + threadIdx.x;
    if (i < T_STEPS * N_NODES) g_degT[i] = 0;
}

__global__ void degT_kernel(const int* __restrict__ graph) {
    int i = blockIdx.x * blockDim.x + threadIdx.x;
    if (i >= T_STEPS * ETOT) return;
    int t = i / ETOT, e = i - t * ETOT;
    int d = (e < E_EDGES) ? graph[(size_t)t * 2 * E_EDGES + E_EDGES + e] : (e - E_EDGES);
    atomicAdd(&g_degT[t * N_NODES + d], 1);
}

__global__ __launch_bounds__(1024) void scanT_kernel() {
    __shared__ int s[1024];
    int t = blockIdx.x;
    const int* deg = g_degT + t * N_NODES;
    int* rowptr = g_rowptrT + t * (N_NODES + 1);
    int* fill = g_fillT + t * N_NODES;
    int tid = threadIdx.x;
    const int PER = 20;
    int base = tid * PER;
    int vals[PER];
    int run = 0;
#pragma unroll
    for (int i = 0; i < PER; i++) {
        int idx = base + i;
        int v = (idx < N_NODES) ? deg[idx] : 0;
        vals[i] = run;
        run += v;
    }
    s[tid] = run;
    __syncthreads();
    for (int off = 1; off < 1024; off <<= 1) {
        int v = (tid >= off) ? s[tid - off] : 0;
        __syncthreads();
        s[tid] += v;
        __syncthreads();
    }
    int prev = (tid == 0) ? 0 : s[tid - 1];
#pragma unroll
    for (int i = 0; i < PER; i++) {
        int idx = base + i;
        if (idx < N_NODES) {
            int r = prev + vals[i];
            rowptr[idx] = r;
            fill[idx] = r;
        }
    }
    if (tid == 1023) rowptr[N_NODES] = s[1023];
}

__global__ void scatterT_kernel(const int* __restrict__ graph) {
    int i = blockIdx.x * blockDim.x + threadIdx.x;
    if (i >= T_STEPS * ETOT) return;
    int t = i / ETOT, e = i - t * ETOT;
    int sidx, d;
    if (e < E_EDGES) {
        sidx = graph[(size_t)t * 2 * E_EDGES + e];
        d    = graph[(size_t)t * 2 * E_EDGES + E_EDGES + e];
    } else {
        sidx = d = e - E_EDGES;
    }
    int pos = atomicAdd(&g_fillT[t * N_NODES + d], 1);
    g_colT[(size_t)t * ETOT + pos] = sidx;
}

// ---------------- 4) aggregation: 8 nodes/block + fused z@W1 + fused final ----------------
__global__ __launch_bounds__(256) void aggregate_kernel(const float* __restrict__ b_gat,
                                                        const float* __restrict__ W1,
                                                        const float* __restrict__ b1,
                                                        const float* __restrict__ W2,
                                                        const float* __restrict__ b2,
                                                        float* __restrict__ out) {
    __shared__ __align__(16) float z_sm[8][C_CH];
    __shared__ float red[2][8];
    int warp = threadIdx.x >> 5;
    int lane = threadIdx.x & 31;
    int t = blockIdx.y;
    int n = blockIdx.x * 8 + warp;

    const int* rowptr = g_rowptrT + t * (N_NODES + 1);
    const int* col = g_colT + (size_t)t * ETOT;
    const float* asrc = g_asrcT + (size_t)t * N_NODES * H_HEADS;
    const uint32_t* h16 = g_h16T + (size_t)t * N_NODES * 256;

    int beg = rowptr[n];
    int end = rowptr[n + 1];
    const float4 ad = *(const float4*)&g_adstT[((size_t)t * N_NODES + n) * H_HEADS];

    float4 acc0 = make_float4(0.f, 0.f, 0.f, 0.f), acc1 = acc0, acc2 = acc0, acc3 = acc0;
    float s0 = 0.f, s1 = 0.f, s2 = 0.f, s3 = 0.f;
    const int lOff = lane * 2;

    int k = beg;
    for (; k + 2 <= end; k += 2) {
        int sa = col[k], sb2 = col[k + 1];
        const float4 ea = *(const float4*)&asrc[sa * H_HEADS];
        const float4 eb = *(const float4*)&asrc[sb2 * H_HEADS];
        float wa0 = __expf(leaky(ea.x + ad.x)), wa1 = __expf(leaky(ea.y + ad.y));
        float wa2 = __expf(leaky(ea.z + ad.z)), wa3 = __expf(leaky(ea.w + ad.w));
        float wb0 = __expf(leaky(eb.x + ad.x)), wb1 = __expf(leaky(eb.y + ad.y));
        float wb2 = __expf(leaky(eb.z + ad.z)), wb3 = __expf(leaky(eb.w + ad.w));
        const uint32_t* ha = h16 + (size_t)sa * 256 + lOff;
        const uint32_t* hb = h16 + (size_t)sb2 * 256 + lOff;
        uint2 ua0 = *(const uint2*)(ha);
        uint2 ua1 = *(const uint2*)(ha + 64);
        uint2 ua2 = *(const uint2*)(ha + 128);
        uint2 ua3 = *(const uint2*)(ha + 192);
        uint2 ub0 = *(const uint2*)(hb);
        uint2 ub1 = *(const uint2*)(hb + 64);
        uint2 ub2 = *(const uint2*)(hb + 128);
        uint2 ub3 = *(const uint2*)(hb + 192);
        s0 += wa0 + wb0; s1 += wa1 + wb1; s2 += wa2 + wb2; s3 += wa3 + wb3;
#define ACCH(ACC, W_A, W_B, UA, UB)                                              \
        {                                                                        \
            float2 la = __bfloat1622float2(*(__nv_bfloat162*)&UA.x);             \
            float2 ha2 = __bfloat1622float2(*(__nv_bfloat162*)&UA.y);            \
            float2 lb = __bfloat1622float2(*(__nv_bfloat162*)&UB.x);             \
            float2 hb2 = __bfloat1622float2(*(__nv_bfloat162*)&UB.y);            \
            ACC.x = fmaf(W_A, la.x, fmaf(W_B, lb.x, ACC.x));                     \
            ACC.y = fmaf(W_A, la.y, fmaf(W_B, lb.y, ACC.y));                     \
            ACC.z = fmaf(W_A, ha2.x, fmaf(W_B, hb2.x, ACC.z));                   \
            ACC.w = fmaf(W_A, ha2.y, fmaf(W_B, hb2.y, ACC.w));                   \
        }
        ACCH(acc0, wa0, wb0, ua0, ub0)
        ACCH(acc1, wa1, wb1, ua1, ub1)
        ACCH(acc2, wa2, wb2, ua2, ub2)
        ACCH(acc3, wa3, wb3, ua3, ub3)
    }
    if (k < end) {
        int sa = col[k];
        const float4 ea = *(const float4*)&asrc[sa * H_HEADS];
        float wa0 = __expf(leaky(ea.x + ad.x)), wa1 = __expf(leaky(ea.y + ad.y));
        float wa2 = __expf(leaky(ea.z + ad.z)), wa3 = __expf(leaky(ea.w + ad.w));
        const uint32_t* ha = h16 + (size_t)sa * 256 + lOff;
        uint2 ua0 = *(const uint2*)(ha);
        uint2 ua1 = *(const uint2*)(ha + 64);
        uint2 ua2 = *(const uint2*)(ha + 128);
        uint2 ua3 = *(const uint2*)(ha + 192);
        s0 += wa0; s1 += wa1; s2 += wa2; s3 += wa3;
#define ACC1(ACC, W_A, UA)                                                       \
        {                                                                        \
            float2 la = __bfloat1622float2(*(__nv_bfloat162*)&UA.x);             \
            float2 ha2 = __bfloat1622float2(*(__nv_bfloat162*)&UA.y);            \
            ACC.x = fmaf(W_A, la.x, ACC.x);                                      \
            ACC.y = fmaf(W_A, la.y, ACC.y);                                      \
            ACC.z = fmaf(W_A, ha2.x, ACC.z);                                     \
            ACC.w = fmaf(W_A, ha2.y, ACC.w);                                     \
        }
        ACC1(acc0, wa0, ua0)
        ACC1(acc1, wa1, ua1)
        ACC1(acc2, wa2, ua2)
        ACC1(acc3, wa3, ua3)
    }
    float i0 = 1.f / (s0 + 1e-16f), i1 = 1.f / (s1 + 1e-16f);
    float i2 = 1.f / (s2 + 1e-16f), i3 = 1.f / (s3 + 1e-16f);

    {
        const float4 bg = *(const float4*)&b_gat[lane * 4];
        float4 z;
        z.x = leaky(0.25f * (acc0.x * i0 + acc1.x * i1 + acc2.x * i2 + acc3.x * i3) + bg.x);
        z.y = leaky(0.25f * (acc0.y * i0 + acc1.y * i1 + acc2.y * i2 + acc3.y * i3) + bg.y);
        z.z = leaky(0.25f * (acc0.z * i0 + acc1.z * i1 + acc2.z * i2 + acc3.z * i3) + bg.z);
        z.w = leaky(0.25f * (acc0.w * i0 + acc1.w * i1 + acc2.w * i2 + acc3.w * i3) + bg.w);
        *(float4*)&z_sm[warp][lane * 4] = z;
    }
    __syncthreads();

    float p0 = 0.f, p1 = 0.f;
    {
        int j    = threadIdx.x & 127;
        int half = threadIdx.x >> 7;
        float a0 = b1[j], a1 = a0, a2 = a0, a3 = a0;
        const float* z0 = z_sm[half * 4 + 0];
        const float* z1 = z_sm[half * 4 + 1];
        const float* z2 = z_sm[half * 4 + 2];
        const float* z3 = z_sm[half * 4 + 3];
#pragma unroll 8
        for (int kk = 0; kk < 128; kk++) {
            float wv = __ldg(&W1[kk * 128 + j]);
            a0 = fmaf(z0[kk], wv, a0);
            a1 = fmaf(z1[kk], wv, a1);
            a2 = fmaf(z2[kk], wv, a2);
            a3 = fmaf(z3[kk], wv, a3);
        }
        float lp[4] = {leaky(a0), leaky(a1), leaky(a2), leaky(a3)};
        int base_i = (half * 4) * 128 + j;
#pragma unroll
        for (int nl = 0; nl < 4; nl++) {
            int i = base_i + nl * 128;
            p0 = fmaf(lp[nl], __ldg(&W2[i * 2 + 0]), p0);
            p1 = fmaf(lp[nl], __ldg(&W2[i * 2 + 1]), p1);
        }
    }
#pragma unroll
    for (int o = 16; o; o >>= 1) {
        p0 += __shfl_xor_sync(0xffffffffu, p0, o);
        p1 += __shfl_xor_sync(0xffffffffu, p1, o);
    }
    if (lane == 0) { red[0][warp] = p0; red[1][warp] = p1; }
    __syncthreads();
    if (threadIdx.x == 0) {
        float f0 = b2[0], f1 = b2[1];
#pragma unroll
        for (int w = 0; w < 8; w++) { f0 += red[0][w]; f1 += red[1][w]; }
        float m = fmaxf(f0, f1);
        float lse = m + logf(expf(f0 - m) + expf(f1 - m));
        int r = t * (N_NODES / 8) + blockIdx.x;
        out[r * 2 + 0] = f0 - lse;
        out[r * 2 + 1] = f1 - lse;
    }
}

// ---------------- launch ----------------
extern "C" void kernel_launch(void* const* d_in, const int* in_sizes, int n_in,
                              void* d_out, int out_size) {
    int base = 2;
    if (n_in >= 11 && in_sizes[2] <= 1) base = 3;

    const float* fts     = (const float*)d_in[0];
    const int*   graph   = (const int*)d_in[1];
    const float* W_gat   = (const float*)d_in[base + 0];
    const float* att_src = (const float*)d_in[base + 1];
    const float* att_dst = (const float*)d_in[base + 2];
    const float* b_gat   = (const float*)d_in[base + 3];
    const float* W1      = (const float*)d_in[base + 4];
    const float* b1      = (const float*)d_in[base + 5];
    const float* W2      = (const float*)d_in[base + 6];
    const float* b2      = (const float*)d_in[base + 7];
    float* out = (float*)d_out;

    cudaFuncSetAttribute(gemm_mma, cudaFuncAttributeMaxDynamicSharedMemorySize, GEMM_SMEM_TOT);

    const int convGrid = (int)(((size_t)T_STEPS * N_NODES * 128 + 255) / 256);

    // gemm_mma kept as the 4th launch for the ncu window
    conv_B<<<(512 * 512 + 255) / 256, 256>>>(W_gat);
    conv_A<<<convGrid, 256>>>(fts);
    zero_degT<<<(T_STEPS * N_NODES + 255) / 256, 256>>>();
    gemm_mma<<<dim3(NT_TILES, MT_TILES, T_STEPS), 256, GEMM_SMEM_TOT>>>(att_src, att_dst);
    degT_kernel<<<(T_STEPS * ETOT + 255) / 256, 256>>>(graph);
    scanT_kernel<<<T_STEPS, 1024>>>();
    scatterT_kernel<<<(T_STEPS * ETOT + 255) / 256, 256>>>(graph);
    aggregate_kernel<<<dim3(N_NODES / 8, T_STEPS), 256>>>(b_gat, W1, b1, W2, b2, out);
}